// round 14
// baseline (speedup 1.0000x reference)
#include <cuda_runtime.h>
#include <cuda_fp16.h>
#include <math.h>

#define MAX_N 100000
#define MAX_E 3200000
#define MAX_G 256
#define HDIM 64
#define NB1024 ((MAX_N + 1023) / 1024)

// ---------------- device scratch ----------------
__device__ __align__(16) int    d_cnt[MAX_N];
__device__ __align__(16) int    d_rowptr[MAX_N + 1];
__device__ __align__(16) int    d_cursor[MAX_N];
__device__ __align__(16) int    d_col[MAX_E];
__device__ __align__(16) float  d_dinv[MAX_N];
__device__ __align__(16) int    d_blocksum[NB1024 + 1];
__device__ __align__(16) float  d_xpad[MAX_N * 8];
__device__ __align__(16) float  d_aggx[MAX_N * 8];
__device__ __align__(16) __half d_hwA[MAX_N * HDIM];
__device__ __align__(16) __half d_hwB[MAX_N * HDIM];
__device__ __align__(16) float  d_psum[MAX_G * HDIM];
__device__ __align__(16) float  d_pcnt[MAX_G];

__device__ __forceinline__ void red_add_v4(float4* addr, float4 v) {
    asm volatile("red.global.add.v4.f32 [%0], {%1,%2,%3,%4};"
                 :: "l"(addr), "f"(v.x), "f"(v.y), "f"(v.z), "f"(v.w)
                 : "memory");
}

// ---------------- prep ----------------
__global__ void zero_kernel(int* cnt, float* psum, float* pcnt, int n, int g) {
    int i = blockIdx.x * blockDim.x + threadIdx.x;
    if (i < n) cnt[i] = 0;
    if (i < g * HDIM) psum[i] = 0.f;
    if (i < g) pcnt[i] = 0.f;
}

__global__ void count_kernel(const int* __restrict__ dst, const int* __restrict__ batch,
                             int* __restrict__ cnt, float* __restrict__ pcnt,
                             int nE, int n) {
    int i = blockIdx.x * blockDim.x + threadIdx.x;
    if (i < nE) atomicAdd(&cnt[dst[i]], 1);
    if (i < n) atomicAdd(&pcnt[batch[i]], 1.f);
}

// phase 1: per-block exclusive scan of cnt; also dinv and xpad = x*dinv
__global__ void scan_phase1(const int* __restrict__ cnt, int* __restrict__ rowptr,
                            int* __restrict__ blocksum, float* __restrict__ dinv,
                            const float* __restrict__ x, float* __restrict__ xpad, int n) {
    __shared__ int ws[32];
    int t = threadIdx.x, lane = t & 31, w = t >> 5;
    int i = blockIdx.x * 1024 + t;
    int v = (i < n) ? cnt[i] : 0;
    if (i < n) {
        float dv = rsqrtf((float)v + 1.0f);
        dinv[i] = dv;
        const float* xr = x + (size_t)i * 5;
        float4* xp = reinterpret_cast<float4*>(xpad + (size_t)i * 8);
        xp[0] = make_float4(xr[0] * dv, xr[1] * dv, xr[2] * dv, xr[3] * dv);
        xp[1] = make_float4(xr[4] * dv, 0.f, 0.f, 0.f);
    }
    int incl = v;
#pragma unroll
    for (int o = 1; o < 32; o <<= 1) {
        int xx = __shfl_up_sync(0xffffffffu, incl, o);
        if (lane >= o) incl += xx;
    }
    if (lane == 31) ws[w] = incl;
    __syncthreads();
    if (w == 0) {
        int xx = ws[lane];
        int incl2 = xx;
#pragma unroll
        for (int o = 1; o < 32; o <<= 1) {
            int y = __shfl_up_sync(0xffffffffu, incl2, o);
            if (lane >= o) incl2 += y;
        }
        ws[lane] = incl2 - xx;
    }
    __syncthreads();
    int excl = incl - v + ws[w];
    if (i < n) rowptr[i] = excl;
    if (t == 1023) blocksum[blockIdx.x] = excl + v;
}

// phase 3: each block reduces its prefix of blocksums itself
__global__ void scan_phase3(int* __restrict__ rowptr, int* __restrict__ cursor,
                            const int* __restrict__ bs, int n, int nE) {
    __shared__ int s_off;
    int t = threadIdx.x;
    if (t < 32) {
        int s = 0;
        for (int q = t; q < blockIdx.x; q += 32) s += bs[q];
#pragma unroll
        for (int o = 16; o; o >>= 1) s += __shfl_down_sync(0xffffffffu, s, o);
        if (t == 0) s_off = s;
    }
    __syncthreads();
    int i = blockIdx.x * 1024 + t;
    int off = s_off;
    if (i < n) { int r = rowptr[i] + off; rowptr[i] = r; cursor[i] = r; }
    if (blockIdx.x == 0 && t == 0) rowptr[n] = nE;
}

// scatter with 4-edge ILP: 4 independent loads -> 4 overlapped atomics -> 4 stores
__global__ void scatter_kernel(const int* __restrict__ src, const int* __restrict__ dst,
                               int* __restrict__ cursor, int* __restrict__ col, int nE) {
    int base = (blockIdx.x * blockDim.x + threadIdx.x) * 4;
    if (base + 4 <= nE) {
        int d0 = __ldg(&dst[base + 0]);
        int d1 = __ldg(&dst[base + 1]);
        int d2 = __ldg(&dst[base + 2]);
        int d3 = __ldg(&dst[base + 3]);
        int s0 = __ldg(&src[base + 0]);
        int s1 = __ldg(&src[base + 1]);
        int s2 = __ldg(&src[base + 2]);
        int s3 = __ldg(&src[base + 3]);
        int i0 = atomicAdd(&cursor[d0], 1);
        int i1 = atomicAdd(&cursor[d1], 1);
        int i2 = atomicAdd(&cursor[d2], 1);
        int i3 = atomicAdd(&cursor[d3], 1);
        col[i0] = s0;
        col[i1] = s1;
        col[i2] = s2;
        col[i3] = s3;
    } else {
        for (int e = base; e < nE; e++) {
            int idx = atomicAdd(&cursor[__ldg(&dst[e])], 1);
            col[idx] = __ldg(&src[e]);
        }
    }
}

// layer-1 aggregation over xpad; 8 thr/node = 4 float2-slots x 2 neighbor halves (R9)
__global__ void aggx_kernel(const int* __restrict__ rowptr, const int* __restrict__ col,
                            const float* __restrict__ dinv,
                            const float2* __restrict__ xp2, float2* __restrict__ out2, int n) {
    int t = blockIdx.x * blockDim.x + threadIdx.x;
    int node = t >> 3;
    int lane = threadIdx.x & 31;
    int half = (lane >> 2) & 1;
    int slot = lane & 3;
    bool valid = (node < n);
    int cn = valid ? node : (n - 1);

    int beg = rowptr[cn], end = rowptr[cn + 1];
    int mid = (beg + end) >> 1;
    int kb = half ? mid : beg;
    int ke = half ? end : mid;

    float2 acc = make_float2(0.f, 0.f);
    if (half == 0) acc = xp2[(size_t)cn * 4 + slot];

    unsigned gmask = 0xFu << (lane & 28);
    int k = kb;
#pragma unroll 1
    for (; k + 4 <= ke; k += 4) {
        int cw = __ldg(&col[k + slot]);
        float2 u[4];
#pragma unroll
        for (int q = 0; q < 4; q++) {
            int c = __shfl_sync(gmask, cw, (lane & 28) + q);
            u[q] = xp2[(size_t)c * 4 + slot];
        }
#pragma unroll
        for (int q = 0; q < 4; q++) { acc.x += u[q].x; acc.y += u[q].y; }
    }
    for (; k < ke; k++) {
        int c = __ldg(&col[k]);
        float2 v = xp2[(size_t)c * 4 + slot];
        acc.x += v.x; acc.y += v.y;
    }
    acc.x += __shfl_xor_sync(0xffffffffu, acc.x, 4);
    acc.y += __shfl_xor_sync(0xffffffffu, acc.y, 4);
    if (valid && half == 0) {
        float dv = dinv[cn];
        out2[(size_t)cn * 4 + slot] = make_float2(acc.x * dv, acc.y * dv);
    }
}

// layer-1 dense chain: h1 = relu(bn1(aggx@W1+b1)); hwA = (h1@W2)*dinv  (fp16)
__global__ __launch_bounds__(256) void l1_fused(
    const float* __restrict__ aggx, const float* __restrict__ W1,
    const float* __restrict__ b1, const float* __restrict__ g1,
    const float* __restrict__ be1, const float* __restrict__ rm1,
    const float* __restrict__ rv1,
    const float* __restrict__ W2, const float* __restrict__ dinv,
    __half* __restrict__ hw, int n) {
    __shared__ float sW1[5][64];
    __shared__ float alphaS[64], betaS[64];
    __shared__ float sA[64][65];
    __shared__ __align__(16) float sW2[64][64];
    int tid = threadIdx.x;
    int bb = blockIdx.x * 64;

    for (int i = tid; i < 320; i += 256) sW1[i >> 6][i & 63] = W1[i];
    for (int i = tid; i < 4096; i += 256) sW2[i >> 6][i & 63] = W2[i];
    if (tid < 64) {
        float alpha = g1[tid] * rsqrtf(rv1[tid] + 1e-5f);
        alphaS[tid] = alpha;
        betaS[tid] = (b1[tid] - rm1[tid]) * alpha + be1[tid];
    }
    __syncthreads();

    {
        int r = tid >> 2, q = tid & 3;
        int node = bb + r;
        float a0 = 0, a1 = 0, a2 = 0, a3 = 0, a4 = 0;
        if (node < n) {
            const float* ar = aggx + (size_t)node * 8;
            a0 = ar[0]; a1 = ar[1]; a2 = ar[2]; a3 = ar[3]; a4 = ar[4];
        }
#pragma unroll
        for (int q2 = 0; q2 < 16; q2++) {
            int c = q * 16 + q2;
            float acc = a0 * sW1[0][c] + a1 * sW1[1][c] + a2 * sW1[2][c]
                      + a3 * sW1[3][c] + a4 * sW1[4][c];
            sA[r][c] = (node < n) ? fmaxf(acc * alphaS[c] + betaS[c], 0.f) : 0.f;
        }
    }
    __syncthreads();

    int tr = (tid >> 4) * 4;
    int tc = (tid & 15) * 4;
    float acc[4][4];
#pragma unroll
    for (int i = 0; i < 4; i++)
#pragma unroll
        for (int j = 0; j < 4; j++) acc[i][j] = 0.f;
#pragma unroll 8
    for (int k = 0; k < 64; k++) {
        float a0 = sA[tr + 0][k], a1 = sA[tr + 1][k], a2 = sA[tr + 2][k], a3 = sA[tr + 3][k];
        float4 b = *reinterpret_cast<const float4*>(&sW2[k][tc]);
        acc[0][0] += a0 * b.x; acc[0][1] += a0 * b.y; acc[0][2] += a0 * b.z; acc[0][3] += a0 * b.w;
        acc[1][0] += a1 * b.x; acc[1][1] += a1 * b.y; acc[1][2] += a1 * b.z; acc[1][3] += a1 * b.w;
        acc[2][0] += a2 * b.x; acc[2][1] += a2 * b.y; acc[2][2] += a2 * b.z; acc[2][3] += a2 * b.w;
        acc[3][0] += a3 * b.x; acc[3][1] += a3 * b.y; acc[3][2] += a3 * b.z; acc[3][3] += a3 * b.w;
    }
#pragma unroll
    for (int i = 0; i < 4; i++) {
        int node = bb + tr + i;
        if (node >= n) break;
        float dv = dinv[node];
        __half2* hp = reinterpret_cast<__half2*>(hw + (size_t)node * HDIM + tc);
        hp[0] = __floats2half2_rn(acc[i][0] * dv, acc[i][1] * dv);
        hp[1] = __floats2half2_rn(acc[i][2] * dv, acc[i][3] * dv);
    }
}

// fused layer-2 (R9 structure, verbatim)
__global__ __launch_bounds__(1024) void agg_gemm(
    const int* __restrict__ rowptr, const int* __restrict__ col,
    const float* __restrict__ dinv, const uint2* __restrict__ hw2,
    const float* __restrict__ b, const float* __restrict__ g,
    const float* __restrict__ be, const float* __restrict__ rm,
    const float* __restrict__ rv,
    const float* __restrict__ W, __half* __restrict__ hw_out, int n) {
    __shared__ float alphaS[64], betaS[64];
    __shared__ float sA[32][65];
    __shared__ __align__(16) float sW[64][64];
    int tid = threadIdx.x;
    int lane = tid & 31;
    int w = tid >> 5;
    int bb = blockIdx.x * 32;

    for (int i = tid; i < 4096; i += 1024) sW[i >> 6][i & 63] = W[i];
    if (tid < 64) {
        float alpha = g[tid] * rsqrtf(rv[tid] + 1e-5f);
        alphaS[tid] = alpha;
        betaS[tid] = (b[tid] - rm[tid]) * alpha + be[tid];
    }
    __syncthreads();

    {
        int node = bb + w;
        int cn = (node < n) ? node : (n - 1);
        int half = lane >> 4;
        int j = lane & 15;
        int beg = rowptr[cn], end = rowptr[cn + 1];
        int mid = (beg + end) >> 1;
        int kb = half ? mid : beg;
        int ke = half ? end : mid;

        float4 acc = make_float4(0.f, 0.f, 0.f, 0.f);
        if (half == 0) {
            uint2 raw = hw2[(size_t)cn * 16 + j];
            float2 f0 = __half22float2(*reinterpret_cast<__half2*>(&raw.x));
            float2 f1 = __half22float2(*reinterpret_cast<__half2*>(&raw.y));
            acc = make_float4(f0.x, f0.y, f1.x, f1.y);
        }
        unsigned gmask = 0xFFFFu << (half << 4);
        int gbase = half << 4;
        int k = kb;
#pragma unroll 1
        for (; k + 8 <= ke; k += 8) {
            int cw = __ldg(&col[k + (j & 7)]);
            uint2 u[8];
#pragma unroll
            for (int q = 0; q < 8; q++) {
                int c = __shfl_sync(gmask, cw, gbase + q);
                u[q] = hw2[(size_t)c * 16 + j];
            }
#pragma unroll
            for (int q = 0; q < 8; q++) {
                float2 a = __half22float2(*reinterpret_cast<__half2*>(&u[q].x));
                float2 bb2 = __half22float2(*reinterpret_cast<__half2*>(&u[q].y));
                acc.x += a.x; acc.y += a.y; acc.z += bb2.x; acc.w += bb2.y;
            }
        }
        for (; k < ke; k++) {
            int c = __ldg(&col[k]);
            uint2 r = hw2[(size_t)c * 16 + j];
            float2 a = __half22float2(*reinterpret_cast<__half2*>(&r.x));
            float2 bb2 = __half22float2(*reinterpret_cast<__half2*>(&r.y));
            acc.x += a.x; acc.y += a.y; acc.z += bb2.x; acc.w += bb2.y;
        }
        acc.x += __shfl_xor_sync(0xffffffffu, acc.x, 16);
        acc.y += __shfl_xor_sync(0xffffffffu, acc.y, 16);
        acc.z += __shfl_xor_sync(0xffffffffu, acc.z, 16);
        acc.w += __shfl_xor_sync(0xffffffffu, acc.w, 16);
        if (half == 0) {
            float dv = dinv[cn];
            int cb = j * 4;
            float in[4] = {acc.x, acc.y, acc.z, acc.w};
#pragma unroll
            for (int q = 0; q < 4; q++) {
                int c = cb + q;
                sA[w][c] = fmaxf(in[q] * dv * alphaS[c] + betaS[c], 0.f);
            }
        }
    }
    __syncthreads();

    {
        int r2 = tid >> 5;
        int c2 = (tid & 31) * 2;
        float o0 = 0.f, o1 = 0.f;
#pragma unroll 8
        for (int k = 0; k < 64; k++) {
            float a = sA[r2][k];
            float2 wv = *reinterpret_cast<const float2*>(&sW[k][c2]);
            o0 += a * wv.x; o1 += a * wv.y;
        }
        int node2 = bb + r2;
        if (node2 < n) {
            float dv2 = dinv[node2];
            reinterpret_cast<__half2*>(hw_out + (size_t)node2 * HDIM)[c2 >> 1]
                = __floats2half2_rn(o0 * dv2, o1 * dv2);
        }
    }
}

// layer-3 (R9 structure, verbatim)
__global__ void agg_pool(const int* __restrict__ rowptr, const int* __restrict__ col,
                         const float* __restrict__ dinv, const uint2* __restrict__ hw2,
                         const float* __restrict__ b, const float* __restrict__ g,
                         const float* __restrict__ be, const float* __restrict__ rm,
                         const float* __restrict__ rv,
                         const int* __restrict__ batch, float4* __restrict__ psum4, int n) {
    int t = blockIdx.x * blockDim.x + threadIdx.x;
    int node = t >> 5;
    int lane = threadIdx.x & 31;
    int half = lane >> 4;
    int j = lane & 15;
    bool valid = (node < n);
    int cn = valid ? node : (n - 1);

    int beg = rowptr[cn], end = rowptr[cn + 1];
    int mid = (beg + end) >> 1;
    int kb = half ? mid : beg;
    int ke = half ? end : mid;

    float4 acc = make_float4(0.f, 0.f, 0.f, 0.f);
    if (half == 0) {
        uint2 raw = hw2[(size_t)cn * 16 + j];
        float2 f0 = __half22float2(*reinterpret_cast<__half2*>(&raw.x));
        float2 f1 = __half22float2(*reinterpret_cast<__half2*>(&raw.y));
        acc = make_float4(f0.x, f0.y, f1.x, f1.y);
    }
    unsigned gmask = 0xFFFFu << (half << 4);
    int gbase = half << 4;
    int k = kb;
#pragma unroll 1
    for (; k + 8 <= ke; k += 8) {
        int cw = __ldg(&col[k + (j & 7)]);
        uint2 u[8];
#pragma unroll
        for (int q = 0; q < 8; q++) {
            int c = __shfl_sync(gmask, cw, gbase + q);
            u[q] = hw2[(size_t)c * 16 + j];
        }
#pragma unroll
        for (int q = 0; q < 8; q++) {
            float2 a = __half22float2(*reinterpret_cast<__half2*>(&u[q].x));
            float2 bb2 = __half22float2(*reinterpret_cast<__half2*>(&u[q].y));
            acc.x += a.x; acc.y += a.y; acc.z += bb2.x; acc.w += bb2.y;
        }
    }
    for (; k < ke; k++) {
        int c = __ldg(&col[k]);
        uint2 r = hw2[(size_t)c * 16 + j];
        float2 a = __half22float2(*reinterpret_cast<__half2*>(&r.x));
        float2 bb2 = __half22float2(*reinterpret_cast<__half2*>(&r.y));
        acc.x += a.x; acc.y += a.y; acc.z += bb2.x; acc.w += bb2.y;
    }
    acc.x += __shfl_xor_sync(0xffffffffu, acc.x, 16);
    acc.y += __shfl_xor_sync(0xffffffffu, acc.y, 16);
    acc.z += __shfl_xor_sync(0xffffffffu, acc.z, 16);
    acc.w += __shfl_xor_sync(0xffffffffu, acc.w, 16);
    if (!valid || half != 0) return;
    float dv = dinv[cn];
    int cb = j * 4;
    float o[4];
    float in[4] = {acc.x * dv, acc.y * dv, acc.z * dv, acc.w * dv};
#pragma unroll
    for (int q = 0; q < 4; q++) {
        int c = cb + q;
        float alpha = g[c] * rsqrtf(rv[c] + 1e-5f);
        float beta = (b[c] - rm[c]) * alpha + be[c];
        o[q] = fmaxf(in[q] * alpha + beta, 0.f);
    }
    int gg = batch[cn];
    red_add_v4(&psum4[gg * 16 + j], make_float4(o[0], o[1], o[2], o[3]));
}

// ---------------- final MLP ----------------
__global__ void mlp_kernel(const float* __restrict__ psum, const float* __restrict__ pcnt,
                           const float* __restrict__ Wf1, const float* __restrict__ bf1,
                           const float* __restrict__ Wf2, const float* __restrict__ bf2,
                           float* __restrict__ out) {
    int g = blockIdx.x;
    int t = threadIdx.x;
    __shared__ float p[64];
    __shared__ float hh[32];
    float cnt = fmaxf(pcnt[g], 1.f);
    float inv = 1.f / cnt;
    p[t] = psum[g * HDIM + t] * inv;
    p[t + 32] = psum[g * HDIM + t + 32] * inv;
    __syncwarp();
    float acc = bf1[t];
#pragma unroll
    for (int k = 0; k < 64; k++)
        acc += p[k] * Wf1[k * 32 + t];
    hh[t] = fmaxf(acc, 0.f);
    __syncwarp();
    if (t < 2) {
        float o = bf2[t];
#pragma unroll
        for (int k = 0; k < 32; k++)
            o += hh[k] * Wf2[k * 2 + t];
        out[g * 2 + t] = 1.f / (1.f + expf(-o));
    }
}

// ---------------- launch ----------------
extern "C" void kernel_launch(void* const* d_in, const int* in_sizes, int n_in,
                              void* d_out, int out_size) {
    const float* x     = (const float*)d_in[0];
    const int*   ei    = (const int*)d_in[1];
    const int*   batch = (const int*)d_in[2];
    const float* W1 = (const float*)d_in[3];
    const float* b1 = (const float*)d_in[4];
    const float* g1 = (const float*)d_in[5];
    const float* be1 = (const float*)d_in[6];
    const float* rm1 = (const float*)d_in[7];
    const float* rv1 = (const float*)d_in[8];
    const float* W2 = (const float*)d_in[9];
    const float* b2 = (const float*)d_in[10];
    const float* g2 = (const float*)d_in[11];
    const float* be2 = (const float*)d_in[12];
    const float* rm2 = (const float*)d_in[13];
    const float* rv2 = (const float*)d_in[14];
    const float* W3 = (const float*)d_in[15];
    const float* b3 = (const float*)d_in[16];
    const float* g3 = (const float*)d_in[17];
    const float* be3 = (const float*)d_in[18];
    const float* rm3 = (const float*)d_in[19];
    const float* rv3 = (const float*)d_in[20];
    const float* Wf1 = (const float*)d_in[21];
    const float* bf1 = (const float*)d_in[22];
    const float* Wf2 = (const float*)d_in[23];
    const float* bf2 = (const float*)d_in[24];

    int n = in_sizes[0] / 5;
    int e = in_sizes[1] / 2;
    int g = out_size / 2;

    const int* srcp = ei;
    const int* dstp = ei + e;

    int *cnt, *rowptr, *cursor, *colp, *bsum;
    float *dinv, *xpad, *aggx, *psum, *pcnt;
    __half *hwA, *hwB;
    cudaGetSymbolAddress((void**)&cnt, d_cnt);
    cudaGetSymbolAddress((void**)&rowptr, d_rowptr);
    cudaGetSymbolAddress((void**)&cursor, d_cursor);
    cudaGetSymbolAddress((void**)&colp, d_col);
    cudaGetSymbolAddress((void**)&bsum, d_blocksum);
    cudaGetSymbolAddress((void**)&dinv, d_dinv);
    cudaGetSymbolAddress((void**)&xpad, d_xpad);
    cudaGetSymbolAddress((void**)&aggx, d_aggx);
    cudaGetSymbolAddress((void**)&hwA, d_hwA);
    cudaGetSymbolAddress((void**)&hwB, d_hwB);
    cudaGetSymbolAddress((void**)&psum, d_psum);
    cudaGetSymbolAddress((void**)&pcnt, d_pcnt);

    const int BS = 256;
    int nb1024 = (n + 1023) / 1024;
    int zero_elems = n > g * HDIM ? n : g * HDIM;

    zero_kernel<<<(zero_elems + BS - 1) / BS, BS>>>(cnt, psum, pcnt, n, g);
    count_kernel<<<(e + BS - 1) / BS, BS>>>(dstp, batch, cnt, pcnt, e, n);
    scan_phase1<<<nb1024, 1024>>>(cnt, rowptr, bsum, dinv, x, xpad, n);
    scan_phase3<<<nb1024, 1024>>>(rowptr, cursor, bsum, n, e);
    scatter_kernel<<<(e / 4 + BS - 1) / BS + 1, BS>>>(srcp, dstp, cursor, colp, e);

    // layer 1
    aggx_kernel<<<((long long)n * 8 + BS - 1) / BS, BS>>>(rowptr, colp, dinv,
                                                          (const float2*)xpad,
                                                          (float2*)aggx, n);
    l1_fused<<<(n + 63) / 64, 256>>>(aggx, W1, b1, g1, be1, rm1, rv1, W2, dinv, hwA, n);

    // layer 2
    agg_gemm<<<(n + 31) / 32, 1024>>>(rowptr, colp, dinv, (const uint2*)hwA,
                                      b2, g2, be2, rm2, rv2, W3, hwB, n);

    // layer 3
    agg_pool<<<((long long)n * 32 + BS - 1) / BS, BS>>>(rowptr, colp, dinv, (const uint2*)hwB,
                                                        b3, g3, be3, rm3, rv3,
                                                        batch, (float4*)psum, n);

    mlp_kernel<<<g, 32>>>(psum, pcnt, Wf1, bf1, Wf2, bf2, (float*)d_out);
}

// round 17
// speedup vs baseline: 1.4545x; 1.4545x over previous
#include <cuda_runtime.h>
#include <cuda_fp16.h>
#include <math.h>

#define MAX_N 100000
#define MAX_E 3200000
#define MAX_G 256
#define HDIM 64
#define NB1024 ((MAX_N + 1023) / 1024)

// ---------------- device scratch ----------------
__device__ __align__(16) int    d_cnt[MAX_N];
__device__ __align__(16) int    d_rowptr[MAX_N + 1];
__device__ __align__(16) int    d_cursor[MAX_N];
__device__ __align__(16) int    d_col[MAX_E];
__device__ __align__(16) float  d_dinv[MAX_N];
__device__ __align__(16) int    d_blocksum[NB1024 + 1];
__device__ __align__(16) float  d_xpad[MAX_N * 8];
__device__ __align__(16) float  d_aggx[MAX_N * 8];
__device__ __align__(16) __half d_hwA[MAX_N * HDIM];
__device__ __align__(16) __half d_hwB[MAX_N * HDIM];
__device__ __align__(16) float  d_psum[MAX_G * HDIM];
__device__ __align__(16) float  d_pcnt[MAX_G];

__device__ __forceinline__ void red_add_v4(float4* addr, float4 v) {
    asm volatile("red.global.add.v4.f32 [%0], {%1,%2,%3,%4};"
                 :: "l"(addr), "f"(v.x), "f"(v.y), "f"(v.z), "f"(v.w)
                 : "memory");
}

// ---------------- prep ----------------
__global__ void zero_kernel(int* cnt, float* psum, float* pcnt, int n, int g) {
    int i = blockIdx.x * blockDim.x + threadIdx.x;
    if (i < n) cnt[i] = 0;
    if (i < g * HDIM) psum[i] = 0.f;
    if (i < g) pcnt[i] = 0.f;
}

__global__ void count_kernel(const int* __restrict__ dst, const int* __restrict__ batch,
                             int* __restrict__ cnt, float* __restrict__ pcnt,
                             int nE, int n) {
    int i = blockIdx.x * blockDim.x + threadIdx.x;
    if (i < nE) atomicAdd(&cnt[dst[i]], 1);
    if (i < n) atomicAdd(&pcnt[batch[i]], 1.f);
}

// phase 1: per-block exclusive scan of cnt; also dinv and xpad = x*dinv
__global__ void scan_phase1(const int* __restrict__ cnt, int* __restrict__ rowptr,
                            int* __restrict__ blocksum, float* __restrict__ dinv,
                            const float* __restrict__ x, float* __restrict__ xpad, int n) {
    __shared__ int ws[32];
    int t = threadIdx.x, lane = t & 31, w = t >> 5;
    int i = blockIdx.x * 1024 + t;
    int v = (i < n) ? cnt[i] : 0;
    if (i < n) {
        float dv = rsqrtf((float)v + 1.0f);
        dinv[i] = dv;
        const float* xr = x + (size_t)i * 5;
        float4* xp = reinterpret_cast<float4*>(xpad + (size_t)i * 8);
        xp[0] = make_float4(xr[0] * dv, xr[1] * dv, xr[2] * dv, xr[3] * dv);
        xp[1] = make_float4(xr[4] * dv, 0.f, 0.f, 0.f);
    }
    int incl = v;
#pragma unroll
    for (int o = 1; o < 32; o <<= 1) {
        int xx = __shfl_up_sync(0xffffffffu, incl, o);
        if (lane >= o) incl += xx;
    }
    if (lane == 31) ws[w] = incl;
    __syncthreads();
    if (w == 0) {
        int xx = ws[lane];
        int incl2 = xx;
#pragma unroll
        for (int o = 1; o < 32; o <<= 1) {
            int y = __shfl_up_sync(0xffffffffu, incl2, o);
            if (lane >= o) incl2 += y;
        }
        ws[lane] = incl2 - xx;
    }
    __syncthreads();
    int excl = incl - v + ws[w];
    if (i < n) rowptr[i] = excl;
    if (t == 1023) blocksum[blockIdx.x] = excl + v;
}

// phase 3: each block reduces its prefix of blocksums itself
__global__ void scan_phase3(int* __restrict__ rowptr, int* __restrict__ cursor,
                            const int* __restrict__ bs, int n, int nE) {
    __shared__ int s_off;
    int t = threadIdx.x;
    if (t < 32) {
        int s = 0;
        for (int q = t; q < blockIdx.x; q += 32) s += bs[q];
#pragma unroll
        for (int o = 16; o; o >>= 1) s += __shfl_down_sync(0xffffffffu, s, o);
        if (t == 0) s_off = s;
    }
    __syncthreads();
    int i = blockIdx.x * 1024 + t;
    int off = s_off;
    if (i < n) { int r = rowptr[i] + off; rowptr[i] = r; cursor[i] = r; }
    if (blockIdx.x == 0 && t == 0) rowptr[n] = nE;
}

__global__ void scatter_kernel(const int* __restrict__ src, const int* __restrict__ dst,
                               int* __restrict__ cursor, int* __restrict__ col, int nE) {
    int e = blockIdx.x * blockDim.x + threadIdx.x;
    if (e >= nE) return;
    int idx = atomicAdd(&cursor[dst[e]], 1);
    col[idx] = src[e];
}

// layer-1 aggregation over xpad; 8 thr/node = 4 float2-slots x 2 neighbor halves
__global__ void aggx_kernel(const int* __restrict__ rowptr, const int* __restrict__ col,
                            const float* __restrict__ dinv,
                            const float2* __restrict__ xp2, float2* __restrict__ out2, int n) {
    int t = blockIdx.x * blockDim.x + threadIdx.x;
    int node = t >> 3;
    int lane = threadIdx.x & 31;
    int half = (lane >> 2) & 1;      // neighbor half
    int slot = lane & 3;             // float2 slot (channels 2s..2s+1)
    bool valid = (node < n);
    int cn = valid ? node : (n - 1);

    int beg = rowptr[cn], end = rowptr[cn + 1];
    int mid = (beg + end) >> 1;
    int kb = half ? mid : beg;
    int ke = half ? end : mid;

    float2 acc = make_float2(0.f, 0.f);
    if (half == 0) acc = xp2[(size_t)cn * 4 + slot];   // self term once

    unsigned gmask = 0xFu << (lane & 28);              // this 4-lane half-group
    int k = kb;
#pragma unroll 1
    for (; k + 4 <= ke; k += 4) {
        int cw = __ldg(&col[k + slot]);
        float2 u[4];
#pragma unroll
        for (int q = 0; q < 4; q++) {
            int c = __shfl_sync(gmask, cw, (lane & 28) + q);
            u[q] = xp2[(size_t)c * 4 + slot];
        }
#pragma unroll
        for (int q = 0; q < 4; q++) { acc.x += u[q].x; acc.y += u[q].y; }
    }
    for (; k < ke; k++) {
        int c = __ldg(&col[k]);
        float2 v = xp2[(size_t)c * 4 + slot];
        acc.x += v.x; acc.y += v.y;
    }
    // combine halves (full-warp sync shuffle; all lanes alive)
    acc.x += __shfl_xor_sync(0xffffffffu, acc.x, 4);
    acc.y += __shfl_xor_sync(0xffffffffu, acc.y, 4);
    if (valid && half == 0) {
        float dv = dinv[cn];
        out2[(size_t)cn * 4 + slot] = make_float2(acc.x * dv, acc.y * dv);
    }
}

// layer-1 dense chain: h1 = relu(bn1(aggx@W1+b1)); hwA = (h1@W2)*dinv  (fp16)
__global__ __launch_bounds__(256) void l1_fused(
    const float* __restrict__ aggx, const float* __restrict__ W1,
    const float* __restrict__ b1, const float* __restrict__ g1,
    const float* __restrict__ be1, const float* __restrict__ rm1,
    const float* __restrict__ rv1,
    const float* __restrict__ W2, const float* __restrict__ dinv,
    __half* __restrict__ hw, int n) {
    __shared__ float sW1[5][64];
    __shared__ float alphaS[64], betaS[64];
    __shared__ float sA[64][65];
    __shared__ __align__(16) float sW2[64][64];
    int tid = threadIdx.x;
    int bb = blockIdx.x * 64;

    for (int i = tid; i < 320; i += 256) sW1[i >> 6][i & 63] = W1[i];
    for (int i = tid; i < 4096; i += 256) sW2[i >> 6][i & 63] = W2[i];
    if (tid < 64) {
        float alpha = g1[tid] * rsqrtf(rv1[tid] + 1e-5f);
        alphaS[tid] = alpha;
        betaS[tid] = (b1[tid] - rm1[tid]) * alpha + be1[tid];
    }
    __syncthreads();

    {
        int r = tid >> 2, q = tid & 3;
        int node = bb + r;
        float a0 = 0, a1 = 0, a2 = 0, a3 = 0, a4 = 0;
        if (node < n) {
            const float* ar = aggx + (size_t)node * 8;
            a0 = ar[0]; a1 = ar[1]; a2 = ar[2]; a3 = ar[3]; a4 = ar[4];
        }
#pragma unroll
        for (int q2 = 0; q2 < 16; q2++) {
            int c = q * 16 + q2;
            float acc = a0 * sW1[0][c] + a1 * sW1[1][c] + a2 * sW1[2][c]
                      + a3 * sW1[3][c] + a4 * sW1[4][c];
            sA[r][c] = (node < n) ? fmaxf(acc * alphaS[c] + betaS[c], 0.f) : 0.f;
        }
    }
    __syncthreads();

    int tr = (tid >> 4) * 4;
    int tc = (tid & 15) * 4;
    float acc[4][4];
#pragma unroll
    for (int i = 0; i < 4; i++)
#pragma unroll
        for (int j = 0; j < 4; j++) acc[i][j] = 0.f;
#pragma unroll 8
    for (int k = 0; k < 64; k++) {
        float a0 = sA[tr + 0][k], a1 = sA[tr + 1][k], a2 = sA[tr + 2][k], a3 = sA[tr + 3][k];
        float4 b = *reinterpret_cast<const float4*>(&sW2[k][tc]);
        acc[0][0] += a0 * b.x; acc[0][1] += a0 * b.y; acc[0][2] += a0 * b.z; acc[0][3] += a0 * b.w;
        acc[1][0] += a1 * b.x; acc[1][1] += a1 * b.y; acc[1][2] += a1 * b.z; acc[1][3] += a1 * b.w;
        acc[2][0] += a2 * b.x; acc[2][1] += a2 * b.y; acc[2][2] += a2 * b.z; acc[2][3] += a2 * b.w;
        acc[3][0] += a3 * b.x; acc[3][1] += a3 * b.y; acc[3][2] += a3 * b.z; acc[3][3] += a3 * b.w;
    }
#pragma unroll
    for (int i = 0; i < 4; i++) {
        int node = bb + tr + i;
        if (node >= n) break;
        float dv = dinv[node];
        __half2* hp = reinterpret_cast<__half2*>(hw + (size_t)node * HDIM + tc);
        hp[0] = __floats2half2_rn(acc[i][0] * dv, acc[i][1] * dv);
        hp[1] = __floats2half2_rn(acc[i][2] * dv, acc[i][3] * dv);
    }
}

// fused layer-2: aggregate hwA (warp/node, split halves) + BN + ReLU + @W3 + *dinv -> hwB
// 1024 threads = 32 warps = 32 nodes per block
__global__ __launch_bounds__(1024) void agg_gemm(
    const int* __restrict__ rowptr, const int* __restrict__ col,
    const float* __restrict__ dinv, const uint2* __restrict__ hw2,
    const float* __restrict__ b, const float* __restrict__ g,
    const float* __restrict__ be, const float* __restrict__ rm,
    const float* __restrict__ rv,
    const float* __restrict__ W, __half* __restrict__ hw_out, int n) {
    __shared__ float alphaS[64], betaS[64];
    __shared__ float sA[32][65];
    __shared__ __align__(16) float sW[64][64];
    int tid = threadIdx.x;
    int lane = tid & 31;
    int w = tid >> 5;               // warp = node slot (0..31)
    int bb = blockIdx.x * 32;

    for (int i = tid; i < 4096; i += 1024) sW[i >> 6][i & 63] = W[i];
    if (tid < 64) {
        float alpha = g[tid] * rsqrtf(rv[tid] + 1e-5f);
        alphaS[tid] = alpha;
        betaS[tid] = (b[tid] - rm[tid]) * alpha + be[tid];
    }
    __syncthreads();

    {
        int node = bb + w;
        int cn = (node < n) ? node : (n - 1);
        int half = lane >> 4;          // neighbor half
        int j = lane & 15;             // channel slot (uint2 = 4 channels)
        int beg = rowptr[cn], end = rowptr[cn + 1];
        int mid = (beg + end) >> 1;
        int kb = half ? mid : beg;
        int ke = half ? end : mid;

        float4 acc = make_float4(0.f, 0.f, 0.f, 0.f);
        if (half == 0) {
            uint2 raw = hw2[(size_t)cn * 16 + j];
            float2 f0 = __half22float2(*reinterpret_cast<__half2*>(&raw.x));
            float2 f1 = __half22float2(*reinterpret_cast<__half2*>(&raw.y));
            acc = make_float4(f0.x, f0.y, f1.x, f1.y);
        }
        unsigned gmask = 0xFFFFu << (half << 4);
        int k = kb;
#pragma unroll 1
        for (; k + 8 <= ke; k += 8) {
            int cw = __ldg(&col[k + (j & 7)]);
            uint2 u[8];
#pragma unroll
            for (int q = 0; q < 8; q++) {
                int c = __shfl_sync(gmask, cw, (half << 4) + q);
                u[q] = hw2[(size_t)c * 16 + j];
            }
#pragma unroll
            for (int q = 0; q < 8; q++) {
                float2 a = __half22float2(*reinterpret_cast<__half2*>(&u[q].x));
                float2 bb2 = __half22float2(*reinterpret_cast<__half2*>(&u[q].y));
                acc.x += a.x; acc.y += a.y; acc.z += bb2.x; acc.w += bb2.y;
            }
        }
        for (; k < ke; k++) {
            int c = __ldg(&col[k]);
            uint2 r = hw2[(size_t)c * 16 + j];
            float2 a = __half22float2(*reinterpret_cast<__half2*>(&r.x));
            float2 bb2 = __half22float2(*reinterpret_cast<__half2*>(&r.y));
            acc.x += a.x; acc.y += a.y; acc.z += bb2.x; acc.w += bb2.y;
        }
        // combine halves
        acc.x += __shfl_xor_sync(0xffffffffu, acc.x, 16);
        acc.y += __shfl_xor_sync(0xffffffffu, acc.y, 16);
        acc.z += __shfl_xor_sync(0xffffffffu, acc.z, 16);
        acc.w += __shfl_xor_sync(0xffffffffu, acc.w, 16);
        if (half == 0) {
            float dv = dinv[cn];
            int cb = j * 4;
            float in[4] = {acc.x, acc.y, acc.z, acc.w};
#pragma unroll
            for (int q = 0; q < 4; q++) {
                int c = cb + q;
                sA[w][c] = fmaxf(in[q] * dv * alphaS[c] + betaS[c], 0.f);
            }
        }
    }
    __syncthreads();

    // GEMM 32x64 @ 64x64: 2 outputs/thread
    {
        int r2 = tid >> 5;             // row = warp id
        int c2 = (tid & 31) * 2;       // 2 consecutive cols
        float o0 = 0.f, o1 = 0.f;
#pragma unroll 8
        for (int k = 0; k < 64; k++) {
            float a = sA[r2][k];
            float2 wv = *reinterpret_cast<const float2*>(&sW[k][c2]);
            o0 += a * wv.x; o1 += a * wv.y;
        }
        int node2 = bb + r2;
        if (node2 < n) {
            float dv2 = dinv[node2];
            reinterpret_cast<__half2*>(hw_out + (size_t)node2 * HDIM)[c2 >> 1]
                = __floats2half2_rn(o0 * dv2, o1 * dv2);
        }
    }
}

// layer-3: aggregate (warp/node, split halves) + BN + ReLU + pool
__global__ void agg_pool(const int* __restrict__ rowptr, const int* __restrict__ col,
                         const float* __restrict__ dinv, const uint2* __restrict__ hw2,
                         const float* __restrict__ b, const float* __restrict__ g,
                         const float* __restrict__ be, const float* __restrict__ rm,
                         const float* __restrict__ rv,
                         const int* __restrict__ batch, float4* __restrict__ psum4, int n) {
    int t = blockIdx.x * blockDim.x + threadIdx.x;
    int node = t >> 5;                 // warp per node
    int lane = threadIdx.x & 31;
    int half = lane >> 4;
    int j = lane & 15;
    bool valid = (node < n);
    int cn = valid ? node : (n - 1);

    int beg = rowptr[cn], end = rowptr[cn + 1];
    int mid = (beg + end) >> 1;
    int kb = half ? mid : beg;
    int ke = half ? end : mid;

    float4 acc = make_float4(0.f, 0.f, 0.f, 0.f);
    if (half == 0) {
        uint2 raw = hw2[(size_t)cn * 16 + j];
        float2 f0 = __half22float2(*reinterpret_cast<__half2*>(&raw.x));
        float2 f1 = __half22float2(*reinterpret_cast<__half2*>(&raw.y));
        acc = make_float4(f0.x, f0.y, f1.x, f1.y);
    }
    unsigned gmask = 0xFFFFu << (half << 4);
    int k = kb;
#pragma unroll 1
    for (; k + 8 <= ke; k += 8) {
        int cw = __ldg(&col[k + (j & 7)]);
        uint2 u[8];
#pragma unroll
        for (int q = 0; q < 8; q++) {
            int c = __shfl_sync(gmask, cw, (half << 4) + q);
            u[q] = hw2[(size_t)c * 16 + j];
        }
#pragma unroll
        for (int q = 0; q < 8; q++) {
            float2 a = __half22float2(*reinterpret_cast<__half2*>(&u[q].x));
            float2 bb2 = __half22float2(*reinterpret_cast<__half2*>(&u[q].y));
            acc.x += a.x; acc.y += a.y; acc.z += bb2.x; acc.w += bb2.y;
        }
    }
    for (; k < ke; k++) {
        int c = __ldg(&col[k]);
        uint2 r = hw2[(size_t)c * 16 + j];
        float2 a = __half22float2(*reinterpret_cast<__half2*>(&r.x));
        float2 bb2 = __half22float2(*reinterpret_cast<__half2*>(&r.y));
        acc.x += a.x; acc.y += a.y; acc.z += bb2.x; acc.w += bb2.y;
    }
    acc.x += __shfl_xor_sync(0xffffffffu, acc.x, 16);
    acc.y += __shfl_xor_sync(0xffffffffu, acc.y, 16);
    acc.z += __shfl_xor_sync(0xffffffffu, acc.z, 16);
    acc.w += __shfl_xor_sync(0xffffffffu, acc.w, 16);
    if (!valid || half != 0) return;
    float dv = dinv[cn];
    int cb = j * 4;
    float o[4];
    float in[4] = {acc.x * dv, acc.y * dv, acc.z * dv, acc.w * dv};
#pragma unroll
    for (int q = 0; q < 4; q++) {
        int c = cb + q;
        float alpha = g[c] * rsqrtf(rv[c] + 1e-5f);
        float beta = (b[c] - rm[c]) * alpha + be[c];
        o[q] = fmaxf(in[q] * alpha + beta, 0.f);
    }
    int gg = batch[cn];
    red_add_v4(&psum4[gg * 16 + j], make_float4(o[0], o[1], o[2], o[3]));
}

// ---------------- final MLP ----------------
__global__ void mlp_kernel(const float* __restrict__ psum, const float* __restrict__ pcnt,
                           const float* __restrict__ Wf1, const float* __restrict__ bf1,
                           const float* __restrict__ Wf2, const float* __restrict__ bf2,
                           float* __restrict__ out) {
    int g = blockIdx.x;
    int t = threadIdx.x;
    __shared__ float p[64];
    __shared__ float hh[32];
    float cnt = fmaxf(pcnt[g], 1.f);
    float inv = 1.f / cnt;
    p[t] = psum[g * HDIM + t] * inv;
    p[t + 32] = psum[g * HDIM + t + 32] * inv;
    __syncwarp();
    float acc = bf1[t];
#pragma unroll
    for (int k = 0; k < 64; k++)
        acc += p[k] * Wf1[k * 32 + t];
    hh[t] = fmaxf(acc, 0.f);
    __syncwarp();
    if (t < 2) {
        float o = bf2[t];
#pragma unroll
        for (int k = 0; k < 32; k++)
            o += hh[k] * Wf2[k * 2 + t];
        out[g * 2 + t] = 1.f / (1.f + expf(-o));
    }
}

// ---------------- launch ----------------
extern "C" void kernel_launch(void* const* d_in, const int* in_sizes, int n_in,
                              void* d_out, int out_size) {
    const float* x     = (const float*)d_in[0];
    const int*   ei    = (const int*)d_in[1];
    const int*   batch = (const int*)d_in[2];
    const float* W1 = (const float*)d_in[3];
    const float* b1 = (const float*)d_in[4];
    const float* g1 = (const float*)d_in[5];
    const float* be1 = (const float*)d_in[6];
    const float* rm1 = (const float*)d_in[7];
    const float* rv1 = (const float*)d_in[8];
    const float* W2 = (const float*)d_in[9];
    const float* b2 = (const float*)d_in[10];
    const float* g2 = (const float*)d_in[11];
    const float* be2 = (const float*)d_in[12];
    const float* rm2 = (const float*)d_in[13];
    const float* rv2 = (const float*)d_in[14];
    const float* W3 = (const float*)d_in[15];
    const float* b3 = (const float*)d_in[16];
    const float* g3 = (const float*)d_in[17];
    const float* be3 = (const float*)d_in[18];
    const float* rm3 = (const float*)d_in[19];
    const float* rv3 = (const float*)d_in[20];
    const float* Wf1 = (const float*)d_in[21];
    const float* bf1 = (const float*)d_in[22];
    const float* Wf2 = (const float*)d_in[23];
    const float* bf2 = (const float*)d_in[24];

    int n = in_sizes[0] / 5;
    int e = in_sizes[1] / 2;
    int g = out_size / 2;

    const int* srcp = ei;
    const int* dstp = ei + e;

    int *cnt, *rowptr, *cursor, *colp, *bsum;
    float *dinv, *xpad, *aggx, *psum, *pcnt;
    __half *hwA, *hwB;
    cudaGetSymbolAddress((void**)&cnt, d_cnt);
    cudaGetSymbolAddress((void**)&rowptr, d_rowptr);
    cudaGetSymbolAddress((void**)&cursor, d_cursor);
    cudaGetSymbolAddress((void**)&colp, d_col);
    cudaGetSymbolAddress((void**)&bsum, d_blocksum);
    cudaGetSymbolAddress((void**)&dinv, d_dinv);
    cudaGetSymbolAddress((void**)&xpad, d_xpad);
    cudaGetSymbolAddress((void**)&aggx, d_aggx);
    cudaGetSymbolAddress((void**)&hwA, d_hwA);
    cudaGetSymbolAddress((void**)&hwB, d_hwB);
    cudaGetSymbolAddress((void**)&psum, d_psum);
    cudaGetSymbolAddress((void**)&pcnt, d_pcnt);

    const int BS = 256;
    int nb1024 = (n + 1023) / 1024;
    int zero_elems = n > g * HDIM ? n : g * HDIM;

    zero_kernel<<<(zero_elems + BS - 1) / BS, BS>>>(cnt, psum, pcnt, n, g);
    count_kernel<<<(e + BS - 1) / BS, BS>>>(dstp, batch, cnt, pcnt, e, n);
    scan_phase1<<<nb1024, 1024>>>(cnt, rowptr, bsum, dinv, x, xpad, n);
    scan_phase3<<<nb1024, 1024>>>(rowptr, cursor, bsum, n, e);
    scatter_kernel<<<(e + BS - 1) / BS, BS>>>(srcp, dstp, cursor, colp, e);

    // layer 1
    aggx_kernel<<<((long long)n * 8 + BS - 1) / BS, BS>>>(rowptr, colp, dinv,
                                                          (const float2*)xpad,
                                                          (float2*)aggx, n);
    l1_fused<<<(n + 63) / 64, 256>>>(aggx, W1, b1, g1, be1, rm1, rv1, W2, dinv, hwA, n);

    // layer 2
    agg_gemm<<<(n + 31) / 32, 1024>>>(rowptr, colp, dinv, (const uint2*)hwA,
                                      b2, g2, be2, rm2, rv2, W3, hwB, n);

    // layer 3
    agg_pool<<<((long long)n * 32 + BS - 1) / BS, BS>>>(rowptr, colp, dinv, (const uint2*)hwB,
                                                        b3, g3, be3, rm3, rv3,
                                                        batch, (float4*)psum, n);

    mlp_kernel<<<g, 32>>>(psum, pcnt, Wf1, bf1, Wf2, bf2, (float*)d_out);
}